// round 16
// baseline (speedup 1.0000x reference)
#include <cuda_runtime.h>
#include <cuda_fp16.h>

#define NN 100000
#define NE 1600000
#define NF 128
#define NH 64
#define NC 16

// ---------------- scratch (static device globals) ----------------
__device__ int    g_ideg[NN];               // in-degree
__device__ int    g_odeg[NN];               // out-degree
__device__ int    g_part[256];              // scan partials (196 used)
__device__ int    g_rowptr[NN + 1];
__device__ int    g_epos[NE];               // within-bucket position per edge
__device__ int    g_col[NE];                // src node per CSR slot
__device__ float  g_ns[NN];                 // rsqrt(max(outdeg,1))
__device__ __half g_h1h[(size_t)NN * NH];   // x@W1 (UNscaled), fp16
__device__ float  g_h2[(size_t)NN * NC];    // (r@W2)*norm_src

#define ADD2(acc, v) asm("add.rn.f32x2 %0, %0, %1;" : "+l"(acc) : "l"(v))

// ---------------- in-degree histogram + position record, 4 edges/thread ----------------
__global__ void k_hist(const int* __restrict__ dst) {
    int i = blockIdx.x * blockDim.x + threadIdx.x;
    if (i * 4 < NE) {
        int4 d = *(const int4*)&dst[i * 4];
        int4 p;
        p.x = atomicAdd(&g_ideg[d.x], 1);
        p.y = atomicAdd(&g_ideg[d.y], 1);
        p.z = atomicAdd(&g_ideg[d.z], 1);
        p.w = atomicAdd(&g_ideg[d.w], 1);
        *(int4*)&g_epos[i * 4] = p;
    }
}

// ---------------- out-degree histogram (main stream), 4 edges/thread ----------------
__global__ void k_ohist(const int* __restrict__ src) {
    int i = blockIdx.x * blockDim.x + threadIdx.x;
    if (i * 4 < NE) {
        int4 s = *(const int4*)&src[i * 4];
        atomicAdd(&g_odeg[s.x], 1);
        atomicAdd(&g_odeg[s.y], 1);
        atomicAdd(&g_odeg[s.z], 1);
        atomicAdd(&g_odeg[s.w], 1);
    }
}

// ---------------- norm_src precompute (needs only odeg) ----------------
__global__ void k_ns() {
    int i = blockIdx.x * blockDim.x + threadIdx.x;
    if (i < NN) g_ns[i] = rsqrtf((float)max(g_odeg[i], 1));
}

// ---------------- scan phase A ----------------
__global__ void __launch_bounds__(256) k_scanA() {
    __shared__ int sh[256];
    const int t = threadIdx.x;
    int i0 = blockIdx.x * 512 + 2 * t;
    int s = 0;
    if (i0 < NN) s += g_ideg[i0];
    if (i0 + 1 < NN) s += g_ideg[i0 + 1];
    sh[t] = s;
    __syncthreads();
    for (int off = 128; off > 0; off >>= 1) {
        if (t < off) sh[t] += sh[t + off];
        __syncthreads();
    }
    if (t == 0) g_part[blockIdx.x] = sh[0];
    if (t == 1 && blockIdx.x == 0) g_rowptr[NN] = NE;
}

// ---------------- scan phase C ----------------
__global__ void __launch_bounds__(256) k_scanC() {
    __shared__ int part[256];
    __shared__ int loc[256];
    const int t = threadIdx.x;
    const int b = blockIdx.x;

    part[t] = (t < 196) ? g_part[t] : 0;
    __syncthreads();
    for (int off = 1; off < 256; off <<= 1) {
        int u = (t >= off) ? part[t - off] : 0;
        __syncthreads();
        part[t] += u;
        __syncthreads();
    }
    int offset = (b > 0) ? part[b - 1] : 0;

    int i0 = b * 512 + 2 * t;
    int d0 = (i0 < NN) ? g_ideg[i0] : 0;
    int d1 = (i0 + 1 < NN) ? g_ideg[i0 + 1] : 0;
    loc[t] = d0 + d1;
    __syncthreads();
    for (int off = 1; off < 256; off <<= 1) {
        int u = (t >= off) ? loc[t - off] : 0;
        __syncthreads();
        loc[t] += u;
        __syncthreads();
    }
    int excl = offset + ((t > 0) ? loc[t - 1] : 0);
    if (i0 < NN)     g_rowptr[i0] = excl;
    if (i0 + 1 < NN) g_rowptr[i0 + 1] = excl + d0;
}

// ---------------- fill CSR: atomic-free, 4 edges/thread ----------------
__global__ void k_fill(const int* __restrict__ src, const int* __restrict__ dst) {
    int i = blockIdx.x * blockDim.x + threadIdx.x;
    if (i * 4 < NE) {
        int4 s = *(const int4*)&src[i * 4];
        int4 d = *(const int4*)&dst[i * 4];
        int4 p = *(const int4*)&g_epos[i * 4];
        g_col[g_rowptr[d.x] + p.x] = s.x;
        g_col[g_rowptr[d.y] + p.y] = s.y;
        g_col[g_rowptr[d.z] + p.z] = s.z;
        g_col[g_rowptr[d.w] + p.w] = s.w;
    }
}

// ---------------- layer-1 GEMM via HMMA: h1h = fp16(x @ W1) (UNscaled) ----------------
#define XH_STRIDE 136                       // halves per row
#define XH_BYTES (128 * XH_STRIDE * 2)      // 34816
#define WF_OFF XH_BYTES
#define GEMM_SMEM (XH_BYTES + 8 * 8 * 32 * 8)   // + 16KB wf = 51200

__global__ void __launch_bounds__(256) k_gemm1(const float* __restrict__ x,
                                               const float* __restrict__ W1) {
    extern __shared__ __align__(16) char sm[];
    __half* xh = (__half*)sm;
    uint2* wf = (uint2*)(sm + WF_OFF);      // [ks][nb][lane]

    const int tid = threadIdx.x;
    const int warp = tid >> 5;
    const int lane = tid & 31;
    const int n0 = blockIdx.x * 128;

    // ---- build W fragments: 2048 uint2, 8 per thread ----
    #pragma unroll
    for (int it = 0; it < 8; it++) {
        int e = tid + it * 256;             // [0,2048)
        int ks = e >> 8;
        int nb = (e >> 5) & 7;
        int ln = e & 31;
        int g = ln >> 2, tc = ln & 3;
        int k0 = ks * 16 + tc * 2;
        int n = nb * 8 + g;
        __half2 b0 = __floats2half2_rn(W1[(size_t)k0 * NH + n],
                                       W1[(size_t)(k0 + 1) * NH + n]);
        __half2 b1 = __floats2half2_rn(W1[(size_t)(k0 + 8) * NH + n],
                                       W1[(size_t)(k0 + 9) * NH + n]);
        uint2 w;
        w.x = *(unsigned*)&b0;
        w.y = *(unsigned*)&b1;
        wf[e] = w;
    }

    // ---- load x (fp32, coalesced LDG.128) -> convert -> fp16 smem ----
    #pragma unroll
    for (int it = 0; it < 16; it++) {
        int idx = tid + it * 256;           // float4 index, [0,4096)
        int node = idx >> 5;
        int k4 = idx & 31;
        int n = n0 + node;
        float4 v = make_float4(0.f, 0.f, 0.f, 0.f);
        if (n < NN) v = *(const float4*)&x[(size_t)n * NF + k4 * 4];
        __half2 h0 = __floats2half2_rn(v.x, v.y);
        __half2 h1 = __floats2half2_rn(v.z, v.w);
        uint2 pkt;
        pkt.x = *(unsigned*)&h0;
        pkt.y = *(unsigned*)&h1;
        *(uint2*)&xh[node * XH_STRIDE + k4 * 4] = pkt;
    }
    __syncthreads();

    // ---- mma mainloop ----
    const int base = warp * 16;
    const int g = lane >> 2, tc = lane & 3;
    float acc[8][4];
    #pragma unroll
    for (int nb = 0; nb < 8; nb++)
        #pragma unroll
        for (int q = 0; q < 4; q++) acc[nb][q] = 0.f;

    #pragma unroll
    for (int ks = 0; ks < 8; ks++) {
        int k0 = ks * 16 + tc * 2;
        unsigned a0 = *(const unsigned*)&xh[(base + g) * XH_STRIDE + k0];
        unsigned a1 = *(const unsigned*)&xh[(base + g + 8) * XH_STRIDE + k0];
        unsigned a2 = *(const unsigned*)&xh[(base + g) * XH_STRIDE + k0 + 8];
        unsigned a3 = *(const unsigned*)&xh[(base + g + 8) * XH_STRIDE + k0 + 8];
        #pragma unroll
        for (int nb = 0; nb < 8; nb++) {
            uint2 b = wf[(ks * 8 + nb) * 32 + lane];
            asm volatile(
                "mma.sync.aligned.m16n8k16.row.col.f32.f16.f16.f32 "
                "{%0,%1,%2,%3}, {%4,%5,%6,%7}, {%8,%9}, {%0,%1,%2,%3};"
                : "+f"(acc[nb][0]), "+f"(acc[nb][1]),
                  "+f"(acc[nb][2]), "+f"(acc[nb][3])
                : "r"(a0), "r"(a1), "r"(a2), "r"(a3), "r"(b.x), "r"(b.y));
        }
    }

    // ---- epilogue -> fp16 ----
    const int n_lo = n0 + base + g;
    const int n_hi = n_lo + 8;
    #pragma unroll
    for (int nb = 0; nb < 8; nb++) {
        int c = nb * 8 + tc * 2;
        if (n_lo < NN) {
            __half2 h = __floats2half2_rn(acc[nb][0], acc[nb][1]);
            *(__half2*)&g_h1h[(size_t)n_lo * NH + c] = h;
        }
        if (n_hi < NN) {
            __half2 h = __floats2half2_rn(acc[nb][2], acc[nb][3]);
            *(__half2*)&g_h1h[(size_t)n_hi * NH + c] = h;
        }
    }
}

// ---------------- fused: gather1 (with per-src ns) + relu + hidden GEMM ----------------
__global__ void __launch_bounds__(256) k_gather1h(const float* __restrict__ b1,
                                                  const float* __restrict__ W2) {
    __shared__ __align__(16) float Rs[32][NH];
    __shared__ __align__(16) float W2s[NH * NC];

    const int tid = threadIdx.x;
    const int nl = tid >> 3;
    const int lane = tid & 7;
    const int g = blockIdx.x * 32 + nl;

    *(float4*)&W2s[tid * 4] = *(const float4*)&W2[tid * 4];

    const int s0 = g_rowptr[g];
    const int s1 = g_rowptr[g + 1];
    float acc[8] = {};

    int j = s0;
    for (; j + 8 <= s1; j += 8) {
        int c[8];
        #pragma unroll
        for (int q = 0; q < 8; q++) c[q] = __ldg(&g_col[j + q]);
        float nsv[8];
        #pragma unroll
        for (int q = 0; q < 8; q++) nsv[q] = __ldg(&g_ns[c[q]]);
        #pragma unroll
        for (int q = 0; q < 8; q++) {
            uint4 v = *(const uint4*)&g_h1h[(size_t)c[q] * NH + lane * 8];
            const __half2* hv = (const __half2*)&v;
            #pragma unroll
            for (int p = 0; p < 4; p++) {
                float2 f = __half22float2(hv[p]);
                acc[2 * p]     = fmaf(f.x, nsv[q], acc[2 * p]);
                acc[2 * p + 1] = fmaf(f.y, nsv[q], acc[2 * p + 1]);
            }
        }
    }
    for (; j < s1; j++) {
        int c = __ldg(&g_col[j]);
        float nsv = __ldg(&g_ns[c]);
        uint4 v = *(const uint4*)&g_h1h[(size_t)c * NH + lane * 8];
        const __half2* hv = (const __half2*)&v;
        #pragma unroll
        for (int p = 0; p < 4; p++) {
            float2 f = __half22float2(hv[p]);
            acc[2 * p]     = fmaf(f.x, nsv, acc[2 * p]);
            acc[2 * p + 1] = fmaf(f.y, nsv, acc[2 * p + 1]);
        }
    }

    float nd = rsqrtf((float)max(s1 - s0, 1));
    float4 bb0 = *(const float4*)&b1[lane * 8];
    float4 bb1 = *(const float4*)&b1[lane * 8 + 4];
    float bv[8] = {bb0.x, bb0.y, bb0.z, bb0.w, bb1.x, bb1.y, bb1.z, bb1.w};
    #pragma unroll
    for (int q = 0; q < 8; q++)
        Rs[nl][lane * 8 + q] = fmaxf(fmaf(acc[q], nd, bv[q]), 0.f);
    __syncthreads();

    const int c0 = lane * 2;
    float a0 = 0.f, a1 = 0.f;
    #pragma unroll
    for (int k = 0; k < NH; k++) {
        float rv = Rs[nl][k];
        float2 w = *(const float2*)&W2s[k * NC + c0];
        a0 = fmaf(rv, w.x, a0);
        a1 = fmaf(rv, w.y, a1);
    }
    float ns = g_ns[g];
    *(float2*)&g_h2[(size_t)g * NC + c0] = make_float2(a0 * ns, a1 * ns);
}

// ---------------- layer-2 gather + log_softmax fused ----------------
__global__ void __launch_bounds__(256) k_gather2(const float* __restrict__ b2,
                                                 float* __restrict__ out) {
    int g0 = blockIdx.x * 64 + (threadIdx.x >> 2);
    const bool valid = (g0 < NN);
    const int g = valid ? g0 : (NN - 1);
    const int lane = threadIdx.x & 3;

    const int s0 = g_rowptr[g];
    const int s1 = g_rowptr[g + 1];
    unsigned long long acc0 = 0ull, acc1 = 0ull;

    int j = s0;
    for (; j + 8 <= s1; j += 8) {
        int c[8];
        #pragma unroll
        for (int q = 0; q < 8; q++) c[q] = __ldg(&g_col[j + q]);
        #pragma unroll
        for (int q = 0; q < 8; q++) {
            ulonglong2 v = *(const ulonglong2*)&g_h2[(size_t)c[q] * NC + lane * 4];
            ADD2(acc0, v.x);
            ADD2(acc1, v.y);
        }
    }
    for (; j < s1; j++) {
        int c = __ldg(&g_col[j]);
        ulonglong2 v = *(const ulonglong2*)&g_h2[(size_t)c * NC + lane * 4];
        ADD2(acc0, v.x);
        ADD2(acc1, v.y);
    }

    float nd = rsqrtf((float)max(s1 - s0, 1));
    float v[4];
    asm("mov.b64 {%0, %1}, %2;" : "=f"(v[0]), "=f"(v[1]) : "l"(acc0));
    asm("mov.b64 {%0, %1}, %2;" : "=f"(v[2]), "=f"(v[3]) : "l"(acc1));
    float4 bb = *(const float4*)&b2[lane * 4];
    v[0] = fmaf(v[0], nd, bb.x);
    v[1] = fmaf(v[1], nd, bb.y);
    v[2] = fmaf(v[2], nd, bb.z);
    v[3] = fmaf(v[3], nd, bb.w);

    float mloc = fmaxf(fmaxf(v[0], v[1]), fmaxf(v[2], v[3]));
    mloc = fmaxf(mloc, __shfl_xor_sync(0xFFFFFFFFu, mloc, 1, 4));
    mloc = fmaxf(mloc, __shfl_xor_sync(0xFFFFFFFFu, mloc, 2, 4));

    float sl = __expf(v[0] - mloc) + __expf(v[1] - mloc) +
               __expf(v[2] - mloc) + __expf(v[3] - mloc);
    sl += __shfl_xor_sync(0xFFFFFFFFu, sl, 1, 4);
    sl += __shfl_xor_sync(0xFFFFFFFFu, sl, 2, 4);
    float l = mloc + __logf(sl);

    if (valid)
        *(float4*)&out[(size_t)g * NC + lane * 4] =
            make_float4(v[0] - l, v[1] - l, v[2] - l, v[3] - l);
}

// ---------------- launch: balanced fork ----------------
extern "C" void kernel_launch(void* const* d_in, const int* in_sizes, int n_in,
                              void* d_out, int out_size) {
    const float* x   = (const float*)d_in[0];
    const int*   src = (const int*)d_in[1];
    const int*   dst = (const int*)d_in[2];
    const float* W1  = (const float*)d_in[3];
    const float* b1  = (const float*)d_in[4];
    const float* W2  = (const float*)d_in[5];
    const float* b2  = (const float*)d_in[6];
    float* out = (float*)d_out;

    cudaFuncSetAttribute(k_gemm1, cudaFuncAttributeMaxDynamicSharedMemorySize,
                         GEMM_SMEM);

    // host-side objects only; intentionally not destroyed.
    cudaStream_t s1;
    cudaStreamCreateWithFlags(&s1, cudaStreamNonBlocking);
    cudaEvent_t evF, evJ;
    cudaEventCreateWithFlags(&evF, cudaEventDisableTiming);
    cudaEventCreateWithFlags(&evJ, cudaEventDisableTiming);

    void *pideg, *podeg;
    cudaGetSymbolAddress(&pideg, g_ideg);
    cudaGetSymbolAddress(&podeg, g_odeg);

    // fork: in-degree CSR chain on s1
    cudaEventRecord(evF, 0);
    cudaStreamWaitEvent(s1, evF, 0);
    cudaMemsetAsync(pideg, 0, (size_t)NN * sizeof(int), s1);
    k_hist<<<(NE / 4 + 255) / 256, 256, 0, s1>>>(dst);
    k_scanA<<<196, 256, 0, s1>>>();
    k_scanC<<<196, 256, 0, s1>>>();
    k_fill<<<(NE / 4 + 255) / 256, 256, 0, s1>>>(src, dst);
    cudaEventRecord(evJ, s1);

    // main stream: dense GEMM (tensor cores) + out-degree + ns
    k_gemm1<<<(NN + 127) / 128, 256, GEMM_SMEM>>>(x, W1);
    cudaMemsetAsync(podeg, 0, (size_t)NN * sizeof(int));
    k_ohist<<<(NE / 4 + 255) / 256, 256>>>(src);
    k_ns<<<(NN + 255) / 256, 256>>>();

    // join, then gather chain
    cudaStreamWaitEvent(0, evJ, 0);
    k_gather1h<<<NN / 32, 256>>>(b1, W2);
    k_gather2<<<(NN + 63) / 64, 256>>>(b2, out);
}

// round 17
// speedup vs baseline: 1.0756x; 1.0756x over previous
#include <cuda_runtime.h>
#include <cuda_fp16.h>

#define NN 100000
#define NE 1600000
#define NF 128
#define NH 64
#define NC 16

// ---------------- scratch (static device globals) ----------------
__device__ int    g_ideg[NN];               // in-degree
__device__ int    g_odeg[NN];               // out-degree
__device__ int    g_part[256];              // scan partials (196 used)
__device__ int    g_rowptr[NN + 1];
__device__ int    g_epos[NE];               // within-bucket position per edge
__device__ int    g_col[NE];                // src node per CSR slot
__device__ float  g_ns[NN];                 // rsqrt(max(outdeg,1))
__device__ __half g_h1h[(size_t)NN * NH];   // (x@W1)*norm_src, fp16
__device__ float  g_h2[(size_t)NN * NC];    // (r@W2)*norm_src

#define ADD2(acc, v) asm("add.rn.f32x2 %0, %0, %1;" : "+l"(acc) : "l"(v))

__device__ __forceinline__ int warp_iscan(int v, int lane) {
    #pragma unroll
    for (int o = 1; o < 32; o <<= 1) {
        int u = __shfl_up_sync(0xFFFFFFFFu, v, o);
        if (lane >= o) v += u;
    }
    return v;
}

// ---------------- in-degree histogram + position record, 4 edges/thread ----------------
__global__ void k_hist(const int* __restrict__ dst) {
    int i = blockIdx.x * blockDim.x + threadIdx.x;
    if (i * 4 < NE) {
        int4 d = *(const int4*)&dst[i * 4];
        int4 p;
        p.x = atomicAdd(&g_ideg[d.x], 1);
        p.y = atomicAdd(&g_ideg[d.y], 1);
        p.z = atomicAdd(&g_ideg[d.z], 1);
        p.w = atomicAdd(&g_ideg[d.w], 1);
        *(int4*)&g_epos[i * 4] = p;
    }
}

// ---------------- out-degree histogram, 4 edges/thread ----------------
__global__ void k_ohist(const int* __restrict__ src) {
    int i = blockIdx.x * blockDim.x + threadIdx.x;
    if (i * 4 < NE) {
        int4 s = *(const int4*)&src[i * 4];
        atomicAdd(&g_odeg[s.x], 1);
        atomicAdd(&g_odeg[s.y], 1);
        atomicAdd(&g_odeg[s.z], 1);
        atomicAdd(&g_odeg[s.w], 1);
    }
}

// ---------------- norm_src precompute ----------------
__global__ void k_ns() {
    int i = blockIdx.x * blockDim.x + threadIdx.x;
    if (i < NN) g_ns[i] = rsqrtf((float)max(g_odeg[i], 1));
}

// ---------------- scan phase A: block sums via shuffle reduce ----------------
__global__ void __launch_bounds__(256) k_scanA() {
    __shared__ int ws[8];
    const int t = threadIdx.x;
    const int lane = t & 31, wid = t >> 5;
    int i0 = blockIdx.x * 512 + 2 * t;
    int s = 0;
    if (i0 < NN) s += g_ideg[i0];
    if (i0 + 1 < NN) s += g_ideg[i0 + 1];
    #pragma unroll
    for (int o = 16; o > 0; o >>= 1) s += __shfl_down_sync(0xFFFFFFFFu, s, o);
    if (lane == 0) ws[wid] = s;
    __syncthreads();
    if (t < 8) {
        int v = ws[t];
        #pragma unroll
        for (int o = 4; o > 0; o >>= 1) v += __shfl_down_sync(0xFFu, v, o, 8);
        if (t == 0) g_part[blockIdx.x] = v;
    }
    if (t == 1 && blockIdx.x == 0) g_rowptr[NN] = NE;
}

// ---------------- scan phase C: shuffle scans ----------------
__global__ void __launch_bounds__(256) k_scanC() {
    __shared__ int ws1[8];
    __shared__ int ws2[8];
    __shared__ int s_off;
    const int t = threadIdx.x;
    const int b = blockIdx.x;
    const int lane = t & 31, wid = t >> 5;

    // scan of partials (196 values over 256 threads)
    int pv = (t < 196) ? g_part[t] : 0;
    int v = warp_iscan(pv, lane);
    if (lane == 31) ws1[wid] = v;

    // local values
    int i0 = b * 512 + 2 * t;
    int d0 = (i0 < NN) ? g_ideg[i0] : 0;
    int d1 = (i0 + 1 < NN) ? g_ideg[i0 + 1] : 0;
    int lv = d0 + d1;
    int v2 = warp_iscan(lv, lane);
    if (lane == 31) ws2[wid] = v2;
    __syncthreads();

    if (wid == 0) {
        int a = (lane < 8) ? ws1[lane] : 0;
        int c = (lane < 8) ? ws2[lane] : 0;
        #pragma unroll
        for (int o = 1; o < 8; o <<= 1) {
            int ua = __shfl_up_sync(0xFFFFFFFFu, a, o);
            int uc = __shfl_up_sync(0xFFFFFFFFu, c, o);
            if (lane >= o) { a += ua; c += uc; }
        }
        if (lane < 8) { ws1[lane] = a; ws2[lane] = c; }
    }
    __syncthreads();

    int incl = v + ((wid > 0) ? ws1[wid - 1] : 0);       // inclusive partials scan
    if (b == 0) { if (t == 0) s_off = 0; }
    else if (t == b - 1) s_off = incl;
    __syncthreads();

    int tot = v2 + ((wid > 0) ? ws2[wid - 1] : 0);       // inclusive local scan
    int excl = s_off + tot - lv;
    if (i0 < NN)     g_rowptr[i0] = excl;
    if (i0 + 1 < NN) g_rowptr[i0 + 1] = excl + d0;
}

// ---------------- fill CSR: atomic-free, 4 edges/thread ----------------
__global__ void k_fill(const int* __restrict__ src, const int* __restrict__ dst) {
    int i = blockIdx.x * blockDim.x + threadIdx.x;
    if (i * 4 < NE) {
        int4 s = *(const int4*)&src[i * 4];
        int4 d = *(const int4*)&dst[i * 4];
        int4 p = *(const int4*)&g_epos[i * 4];
        g_col[g_rowptr[d.x] + p.x] = s.x;
        g_col[g_rowptr[d.y] + p.y] = s.y;
        g_col[g_rowptr[d.z] + p.z] = s.z;
        g_col[g_rowptr[d.w] + p.w] = s.w;
    }
}

// ---------------- layer-1 GEMM via HMMA: h1h = fp16((x @ W1) * norm_src) ----------------
#define XH_STRIDE 136                       // halves per row
#define XH_BYTES (128 * XH_STRIDE * 2)      // 34816
#define WF_OFF XH_BYTES
#define GEMM_SMEM (XH_BYTES + 8 * 8 * 32 * 8)   // + 16KB wf = 51200

__global__ void __launch_bounds__(256) k_gemm1(const float* __restrict__ x,
                                               const float* __restrict__ W1) {
    extern __shared__ __align__(16) char sm[];
    __half* xh = (__half*)sm;
    uint2* wf = (uint2*)(sm + WF_OFF);      // [ks][nb][lane]

    const int tid = threadIdx.x;
    const int warp = tid >> 5;
    const int lane = tid & 31;
    const int n0 = blockIdx.x * 128;

    // ---- build W fragments: 2048 uint2, 8 per thread ----
    #pragma unroll
    for (int it = 0; it < 8; it++) {
        int e = tid + it * 256;             // [0,2048)
        int ks = e >> 8;
        int nb = (e >> 5) & 7;
        int ln = e & 31;
        int g = ln >> 2, tc = ln & 3;
        int k0 = ks * 16 + tc * 2;
        int n = nb * 8 + g;
        __half2 b0 = __floats2half2_rn(W1[(size_t)k0 * NH + n],
                                       W1[(size_t)(k0 + 1) * NH + n]);
        __half2 b1 = __floats2half2_rn(W1[(size_t)(k0 + 8) * NH + n],
                                       W1[(size_t)(k0 + 9) * NH + n]);
        uint2 w;
        w.x = *(unsigned*)&b0;
        w.y = *(unsigned*)&b1;
        wf[e] = w;
    }

    // ---- load x (fp32, coalesced LDG.128) -> convert -> fp16 smem ----
    #pragma unroll
    for (int it = 0; it < 16; it++) {
        int idx = tid + it * 256;
        int node = idx >> 5;
        int k4 = idx & 31;
        int n = n0 + node;
        float4 v = make_float4(0.f, 0.f, 0.f, 0.f);
        if (n < NN) v = *(const float4*)&x[(size_t)n * NF + k4 * 4];
        __half2 h0 = __floats2half2_rn(v.x, v.y);
        __half2 h1 = __floats2half2_rn(v.z, v.w);
        uint2 pkt;
        pkt.x = *(unsigned*)&h0;
        pkt.y = *(unsigned*)&h1;
        *(uint2*)&xh[node * XH_STRIDE + k4 * 4] = pkt;
    }
    __syncthreads();

    // ---- mma mainloop ----
    const int base = warp * 16;
    const int g = lane >> 2, tc = lane & 3;
    float acc[8][4];
    #pragma unroll
    for (int nb = 0; nb < 8; nb++)
        #pragma unroll
        for (int q = 0; q < 4; q++) acc[nb][q] = 0.f;

    #pragma unroll
    for (int ks = 0; ks < 8; ks++) {
        int k0 = ks * 16 + tc * 2;
        unsigned a0 = *(const unsigned*)&xh[(base + g) * XH_STRIDE + k0];
        unsigned a1 = *(const unsigned*)&xh[(base + g + 8) * XH_STRIDE + k0];
        unsigned a2 = *(const unsigned*)&xh[(base + g) * XH_STRIDE + k0 + 8];
        unsigned a3 = *(const unsigned*)&xh[(base + g + 8) * XH_STRIDE + k0 + 8];
        #pragma unroll
        for (int nb = 0; nb < 8; nb++) {
            uint2 b = wf[(ks * 8 + nb) * 32 + lane];
            asm volatile(
                "mma.sync.aligned.m16n8k16.row.col.f32.f16.f16.f32 "
                "{%0,%1,%2,%3}, {%4,%5,%6,%7}, {%8,%9}, {%0,%1,%2,%3};"
                : "+f"(acc[nb][0]), "+f"(acc[nb][1]),
                  "+f"(acc[nb][2]), "+f"(acc[nb][3])
                : "r"(a0), "r"(a1), "r"(a2), "r"(a3), "r"(b.x), "r"(b.y));
        }
    }

    // ---- epilogue: scale by norm_src, cvt fp16 ----
    const int n_lo = n0 + base + g;
    const int n_hi = n_lo + 8;
    float s_lo = (n_lo < NN) ? g_ns[n_lo] : 0.f;
    float s_hi = (n_hi < NN) ? g_ns[n_hi] : 0.f;
    #pragma unroll
    for (int nb = 0; nb < 8; nb++) {
        int c = nb * 8 + tc * 2;
        if (n_lo < NN) {
            __half2 h = __floats2half2_rn(acc[nb][0] * s_lo, acc[nb][1] * s_lo);
            *(__half2*)&g_h1h[(size_t)n_lo * NH + c] = h;
        }
        if (n_hi < NN) {
            __half2 h = __floats2half2_rn(acc[nb][2] * s_hi, acc[nb][3] * s_hi);
            *(__half2*)&g_h1h[(size_t)n_hi * NH + c] = h;
        }
    }
}

// ---------------- fused: gather1 + relu + hidden GEMM -> h2 ----------------
__global__ void __launch_bounds__(256) k_gather1h(const float* __restrict__ b1,
                                                  const float* __restrict__ W2) {
    __shared__ __align__(16) float Rs[32][NH];
    __shared__ __align__(16) float W2s[NH * NC];

    const int tid = threadIdx.x;
    const int nl = tid >> 3;
    const int lane = tid & 7;
    const int g = blockIdx.x * 32 + nl;

    *(float4*)&W2s[tid * 4] = *(const float4*)&W2[tid * 4];

    const int s0 = g_rowptr[g];
    const int s1 = g_rowptr[g + 1];
    float acc[8] = {};

    int j = s0;
    for (; j + 8 <= s1; j += 8) {
        int c[8];
        #pragma unroll
        for (int q = 0; q < 8; q++) c[q] = __ldg(&g_col[j + q]);
        #pragma unroll
        for (int q = 0; q < 8; q++) {
            uint4 v = *(const uint4*)&g_h1h[(size_t)c[q] * NH + lane * 8];
            const __half2* hv = (const __half2*)&v;
            #pragma unroll
            for (int p = 0; p < 4; p++) {
                float2 f = __half22float2(hv[p]);
                acc[2 * p] += f.x;
                acc[2 * p + 1] += f.y;
            }
        }
    }
    for (; j < s1; j++) {
        int c = __ldg(&g_col[j]);
        uint4 v = *(const uint4*)&g_h1h[(size_t)c * NH + lane * 8];
        const __half2* hv = (const __half2*)&v;
        #pragma unroll
        for (int p = 0; p < 4; p++) {
            float2 f = __half22float2(hv[p]);
            acc[2 * p] += f.x;
            acc[2 * p + 1] += f.y;
        }
    }

    float nd = rsqrtf((float)max(s1 - s0, 1));
    float4 bb0 = *(const float4*)&b1[lane * 8];
    float4 bb1 = *(const float4*)&b1[lane * 8 + 4];
    float bv[8] = {bb0.x, bb0.y, bb0.z, bb0.w, bb1.x, bb1.y, bb1.z, bb1.w};
    #pragma unroll
    for (int q = 0; q < 8; q++)
        Rs[nl][lane * 8 + q] = fmaxf(fmaf(acc[q], nd, bv[q]), 0.f);
    __syncthreads();

    const int c0 = lane * 2;
    float a0 = 0.f, a1 = 0.f;
    #pragma unroll
    for (int k = 0; k < NH; k++) {
        float rv = Rs[nl][k];
        float2 w = *(const float2*)&W2s[k * NC + c0];
        a0 = fmaf(rv, w.x, a0);
        a1 = fmaf(rv, w.y, a1);
    }
    float ns = g_ns[g];
    *(float2*)&g_h2[(size_t)g * NC + c0] = make_float2(a0 * ns, a1 * ns);
}

// ---------------- layer-2 gather + log_softmax fused ----------------
__global__ void __launch_bounds__(256) k_gather2(const float* __restrict__ b2,
                                                 float* __restrict__ out) {
    int g0 = blockIdx.x * 64 + (threadIdx.x >> 2);
    const bool valid = (g0 < NN);
    const int g = valid ? g0 : (NN - 1);
    const int lane = threadIdx.x & 3;

    const int s0 = g_rowptr[g];
    const int s1 = g_rowptr[g + 1];
    unsigned long long acc0 = 0ull, acc1 = 0ull;

    int j = s0;
    for (; j + 8 <= s1; j += 8) {
        int c[8];
        #pragma unroll
        for (int q = 0; q < 8; q++) c[q] = __ldg(&g_col[j + q]);
        #pragma unroll
        for (int q = 0; q < 8; q++) {
            ulonglong2 v = *(const ulonglong2*)&g_h2[(size_t)c[q] * NC + lane * 4];
            ADD2(acc0, v.x);
            ADD2(acc1, v.y);
        }
    }
    for (; j < s1; j++) {
        int c = __ldg(&g_col[j]);
        ulonglong2 v = *(const ulonglong2*)&g_h2[(size_t)c * NC + lane * 4];
        ADD2(acc0, v.x);
        ADD2(acc1, v.y);
    }

    float nd = rsqrtf((float)max(s1 - s0, 1));
    float v[4];
    asm("mov.b64 {%0, %1}, %2;" : "=f"(v[0]), "=f"(v[1]) : "l"(acc0));
    asm("mov.b64 {%0, %1}, %2;" : "=f"(v[2]), "=f"(v[3]) : "l"(acc1));
    float4 bb = *(const float4*)&b2[lane * 4];
    v[0] = fmaf(v[0], nd, bb.x);
    v[1] = fmaf(v[1], nd, bb.y);
    v[2] = fmaf(v[2], nd, bb.z);
    v[3] = fmaf(v[3], nd, bb.w);

    float mloc = fmaxf(fmaxf(v[0], v[1]), fmaxf(v[2], v[3]));
    mloc = fmaxf(mloc, __shfl_xor_sync(0xFFFFFFFFu, mloc, 1, 4));
    mloc = fmaxf(mloc, __shfl_xor_sync(0xFFFFFFFFu, mloc, 2, 4));

    float sl = __expf(v[0] - mloc) + __expf(v[1] - mloc) +
               __expf(v[2] - mloc) + __expf(v[3] - mloc);
    sl += __shfl_xor_sync(0xFFFFFFFFu, sl, 1, 4);
    sl += __shfl_xor_sync(0xFFFFFFFFu, sl, 2, 4);
    float l = mloc + __logf(sl);

    if (valid)
        *(float4*)&out[(size_t)g * NC + lane * 4] =
            make_float4(v[0] - l, v[1] - l, v[2] - l, v[3] - l);
}

// ---------------- launch ----------------
extern "C" void kernel_launch(void* const* d_in, const int* in_sizes, int n_in,
                              void* d_out, int out_size) {
    const float* x   = (const float*)d_in[0];
    const int*   src = (const int*)d_in[1];
    const int*   dst = (const int*)d_in[2];
    const float* W1  = (const float*)d_in[3];
    const float* b1  = (const float*)d_in[4];
    const float* W2  = (const float*)d_in[5];
    const float* b2  = (const float*)d_in[6];
    float* out = (float*)d_out;

    cudaFuncSetAttribute(k_gemm1, cudaFuncAttributeMaxDynamicSharedMemorySize,
                         GEMM_SMEM);

    // host-side objects only; intentionally not destroyed.
    cudaStream_t s1;
    cudaStreamCreateWithFlags(&s1, cudaStreamNonBlocking);
    cudaEvent_t evF, evJ;
    cudaEventCreateWithFlags(&evF, cudaEventDisableTiming);
    cudaEventCreateWithFlags(&evJ, cudaEventDisableTiming);

    void *pideg, *podeg;
    cudaGetSymbolAddress(&pideg, g_ideg);
    cudaGetSymbolAddress(&podeg, g_odeg);

    // fork: in-degree CSR chain on s1
    cudaEventRecord(evF, 0);
    cudaStreamWaitEvent(s1, evF, 0);
    cudaMemsetAsync(pideg, 0, (size_t)NN * sizeof(int), s1);
    k_hist<<<(NE / 4 + 255) / 256, 256, 0, s1>>>(dst);
    k_scanA<<<196, 256, 0, s1>>>();
    k_scanC<<<196, 256, 0, s1>>>();
    k_fill<<<(NE / 4 + 255) / 256, 256, 0, s1>>>(src, dst);
    cudaEventRecord(evJ, s1);

    // main stream: out-degree + ns first (gemm1 consumes ns), then HMMA GEMM
    cudaMemsetAsync(podeg, 0, (size_t)NN * sizeof(int));
    k_ohist<<<(NE / 4 + 255) / 256, 256>>>(src);
    k_ns<<<(NN + 255) / 256, 256>>>();
    k_gemm1<<<(NN + 127) / 128, 256, GEMM_SMEM>>>(x, W1);

    // join, then gather chain
    cudaStreamWaitEvent(0, evJ, 0);
    k_gather1h<<<NN / 32, 256>>>(b1, W2);
    k_gather2<<<(NN + 63) / 64, 256>>>(b2, out);
}